// round 4
// baseline (speedup 1.0000x reference)
#include <cuda_runtime.h>
#include <cstdint>

#define NU 200000
#define NM 80000
#define NN 280000            // real nodes
#define NP 280064            // padded to 2188*128
#define H  64

// ---------------- scratch (device globals; no allocation allowed) ----------
__device__ float g_X0[(size_t)NP * H];    // node features layer-in / final out
__device__ float g_X1[(size_t)NP * H];    // layer-1 output
__device__ float g_AGGa[(size_t)NP * 32]; // scatter accumulator, cols 0-31
__device__ float g_AGGb[(size_t)NP * 32]; // scatter accumulator, cols 32-63
__device__ float g_DEG[NP];
__device__ float g_INV[NP];
__device__ int   g_flag32[1];             // 1 => indices are int32, 0 => int64

// ---------------- index dtype detection ------------------------------------
__global__ void k_zero_flag() { g_flag32[0] = 0; }

__global__ void k_detect(const long long* __restrict__ ei, int ncheck) {
    int i = blockIdx.x * blockDim.x + threadIdx.x;
    if (i < ncheck) {
        long long v = ei[i];
        if (v < 0 || v >= (long long)NN) atomicOr(g_flag32, 1);
    }
}

__device__ __forceinline__ int get_idx(const void* ei, int pos, int f32) {
    if (f32) return ((const int*)ei)[pos];
    return (int)((const long long*)ei)[pos];
}

// ---------------- node init -------------------------------------------------
__global__ void k_init_movie(const float* __restrict__ movie_x,
                             const float* __restrict__ lin_W,
                             const float* __restrict__ lin_b,
                             const float* __restrict__ movie_emb,
                             float* __restrict__ X0) {
    int t = blockIdx.x * blockDim.x + threadIdx.x;
    if (t >= NM * H) return;
    int m = t >> 6, j = t & 63;
    float acc = __ldg(&lin_b[j]);
#pragma unroll
    for (int k = 0; k < 20; ++k)
        acc += __ldg(&movie_x[m * 20 + k]) * __ldg(&lin_W[j * 20 + k]);
    X0[(size_t)(NU + m) * H + j] = acc + __ldg(&movie_emb[t]);
}

// ---------------- degree / inverse ------------------------------------------
__global__ void k_deg(const void* __restrict__ ei, int E) {
    int e = blockIdx.x * blockDim.x + threadIdx.x;
    if (e >= E) return;
    int f = g_flag32[0];
    int dst = get_idx(ei, E + e, f);
    atomicAdd(&g_DEG[dst], 1.0f);
}

__global__ void k_inv() {
    int i = blockIdx.x * blockDim.x + threadIdx.x;
    if (i < NP) g_INV[i] = 1.0f / fmaxf(g_DEG[i], 1.0f);
}

// ---------------- scatter (half feature-dim per pass) -----------------------
// AGG_half[dst][0..31] += X[src][off..off+31].  8 threads/edge, float4 chunks.
// Working set per pass: 35.8MB X-half + 35.8MB AGG-half => L2-resident.
__global__ void k_scatter_half(const float4* __restrict__ X,
                               const void* __restrict__ ei, int E,
                               float* __restrict__ AGG_half, int off4) {
    int t = blockIdx.x * blockDim.x + threadIdx.x;
    if (t >= E * 8) return;
    int e = t >> 3, c = t & 7;
    int f = g_flag32[0];
    int src = get_idx(ei, e, f);
    int dst = get_idx(ei, E + e, f);
    float4 v = __ldg(&X[(size_t)src * 16 + off4 + c]);
    float* p = &AGG_half[(size_t)dst * 32 + c * 4];
    asm volatile("red.global.add.v4.f32 [%0], {%1,%2,%3,%4};"
                 :: "l"(p), "f"(v.x), "f"(v.y), "f"(v.z), "f"(v.w)
                 : "memory");
}

// ---------------- tf32 helpers ----------------------------------------------
__device__ __forceinline__ uint32_t f2tf32(float x) {
    uint32_t r;
    asm("cvt.rna.tf32.f32 %0, %1;" : "=r"(r) : "f"(x));
    return r;
}

// ---------------- dense update via tensor cores ------------------------------
// out = [mean‖x](NP x 128) @ Wc(128 x 64) + b, mean from split AGG halves.
__global__ void __launch_bounds__(256)
k_dense_mma(const float* __restrict__ AGGa, const float* __restrict__ AGGb,
            const float* __restrict__ Xin,
            const float* __restrict__ Wl, const float* __restrict__ bvec,
            const float* __restrict__ Wr, float* __restrict__ Xout,
            int do_relu) {
    __shared__ uint32_t Bs[128][72];
    __shared__ float invs[128];
    __shared__ float bsh[64];

    int tid  = threadIdx.x;
    int base = blockIdx.x * 128;

    for (int i = tid; i < 128 * 64; i += 256) {
        int k = i & 127, j = i >> 7;
        float w = (k < 64) ? __ldg(&Wl[j * 64 + k]) : __ldg(&Wr[j * 64 + k - 64]);
        Bs[k][j] = f2tf32(w);
    }
    if (tid < 128) invs[tid] = g_INV[base + tid];
    if (tid < 64)  bsh[tid]  = __ldg(&bvec[tid]);
    __syncthreads();

    int warp = tid >> 5, lane = tid & 31;
    int r = lane >> 2, c = lane & 3;
    int row0 = base + warp * 16 + r;        // rows row0, row0+8
    float iv0 = invs[warp * 16 + r];
    float iv1 = invs[warp * 16 + r + 8];

    float acc[8][4];
#pragma unroll
    for (int nf = 0; nf < 8; ++nf)
#pragma unroll
        for (int i = 0; i < 4; ++i) acc[nf][i] = 0.0f;

    const float* Aa0 = AGGa + (size_t)row0 * 32;
    const float* Aa1 = AGGa + (size_t)(row0 + 8) * 32;
    const float* Ab0 = AGGb + (size_t)row0 * 32;
    const float* Ab1 = AGGb + (size_t)(row0 + 8) * 32;
    const float* X0p = Xin + (size_t)row0 * 64;
    const float* X1p = Xin + (size_t)(row0 + 8) * 64;

#pragma unroll
    for (int ks = 0; ks < 16; ++ks) {
        int k0 = ks * 8;
        uint32_t a0, a1, a2, a3;
        if (ks < 4) {
            a0 = f2tf32(__ldg(&Aa0[k0 + c])     * iv0);
            a1 = f2tf32(__ldg(&Aa1[k0 + c])     * iv1);
            a2 = f2tf32(__ldg(&Aa0[k0 + c + 4]) * iv0);
            a3 = f2tf32(__ldg(&Aa1[k0 + c + 4]) * iv1);
        } else if (ks < 8) {
            int kk = k0 - 32;
            a0 = f2tf32(__ldg(&Ab0[kk + c])     * iv0);
            a1 = f2tf32(__ldg(&Ab1[kk + c])     * iv1);
            a2 = f2tf32(__ldg(&Ab0[kk + c + 4]) * iv0);
            a3 = f2tf32(__ldg(&Ab1[kk + c + 4]) * iv1);
        } else {
            int kk = k0 - 64;
            a0 = f2tf32(__ldg(&X0p[kk + c]));
            a1 = f2tf32(__ldg(&X1p[kk + c]));
            a2 = f2tf32(__ldg(&X0p[kk + c + 4]));
            a3 = f2tf32(__ldg(&X1p[kk + c + 4]));
        }
#pragma unroll
        for (int nf = 0; nf < 8; ++nf) {
            uint32_t b0 = Bs[k0 + c][8 * nf + r];
            uint32_t b1 = Bs[k0 + c + 4][8 * nf + r];
            asm volatile(
                "mma.sync.aligned.m16n8k8.row.col.f32.tf32.tf32.f32 "
                "{%0,%1,%2,%3}, {%4,%5,%6,%7}, {%8,%9}, {%0,%1,%2,%3};"
                : "+f"(acc[nf][0]), "+f"(acc[nf][1]),
                  "+f"(acc[nf][2]), "+f"(acc[nf][3])
                : "r"(a0), "r"(a1), "r"(a2), "r"(a3), "r"(b0), "r"(b1));
        }
    }

#pragma unroll
    for (int nf = 0; nf < 8; ++nf) {
        int col = 8 * nf + 2 * c;
        float o0 = acc[nf][0] + bsh[col];
        float o1 = acc[nf][1] + bsh[col + 1];
        float o2 = acc[nf][2] + bsh[col];
        float o3 = acc[nf][3] + bsh[col + 1];
        if (do_relu) {
            o0 = fmaxf(o0, 0.0f); o1 = fmaxf(o1, 0.0f);
            o2 = fmaxf(o2, 0.0f); o3 = fmaxf(o3, 0.0f);
        }
        *(float2*)&Xout[(size_t)row0 * 64 + col]       = make_float2(o0, o1);
        *(float2*)&Xout[(size_t)(row0 + 8) * 64 + col] = make_float2(o2, o3);
    }
}

// ---------------- scoring ---------------------------------------------------
__global__ void k_score(const float* __restrict__ X,
                        const void* __restrict__ eli,
                        float* __restrict__ out, int EL) {
    int t = blockIdx.x * blockDim.x + threadIdx.x;
    if (t >= EL * 16) return;
    int e = t >> 4, c = t & 15;
    int f = g_flag32[0];
    int u = get_idx(eli, e, f);
    int m = get_idx(eli, EL + e, f);
    const float4* X4 = (const float4*)X;
    float4 a = __ldg(&X4[(size_t)u * 16 + c]);
    float4 b = __ldg(&X4[(size_t)(NU + m) * 16 + c]);
    float p = a.x * b.x + a.y * b.y + a.z * b.z + a.w * b.w;
    p += __shfl_xor_sync(0xffffffffu, p, 8);
    p += __shfl_xor_sync(0xffffffffu, p, 4);
    p += __shfl_xor_sync(0xffffffffu, p, 2);
    p += __shfl_xor_sync(0xffffffffu, p, 1);
    if (c == 0) out[e] = p;
}

// ---------------- launch ----------------------------------------------------
extern "C" void kernel_launch(void* const* d_in, const int* in_sizes, int n_in,
                              void* d_out, int out_size) {
    const float* movie_x   = (const float*)d_in[0];
    const float* lin_W     = (const float*)d_in[3];
    const float* lin_b     = (const float*)d_in[4];
    const float* movie_emb = (const float*)d_in[2];
    const float* W1l = (const float*)d_in[5];
    const float* b1  = (const float*)d_in[6];
    const float* W1r = (const float*)d_in[7];
    const float* W2l = (const float*)d_in[8];
    const float* b2  = (const float*)d_in[9];
    const float* W2r = (const float*)d_in[10];
    const void*  ei  = d_in[11];
    const void*  eli = d_in[12];
    int E  = in_sizes[11] / 2;
    int EL = in_sizes[12] / 2;

    void *pX0, *pX1, *pAGGa, *pAGGb, *pDEG;
    cudaGetSymbolAddress(&pX0, g_X0);
    cudaGetSymbolAddress(&pX1, g_X1);
    cudaGetSymbolAddress(&pAGGa, g_AGGa);
    cudaGetSymbolAddress(&pAGGb, g_AGGb);
    cudaGetSymbolAddress(&pDEG, g_DEG);

    const size_t HALF = (size_t)NP * 32 * sizeof(float);

    cudaMemsetAsync(pDEG, 0, (size_t)NP * sizeof(float), 0);

    k_zero_flag<<<1, 1>>>();
    k_detect<<<4, 256>>>((const long long*)ei, 1024);

    // node features
    cudaMemcpyAsync(pX0, d_in[1], (size_t)NU * H * sizeof(float),
                    cudaMemcpyDeviceToDevice, 0);
    k_init_movie<<<(NM * H + 255) / 256, 256>>>(movie_x, lin_W, lin_b,
                                                movie_emb, (float*)pX0);

    // degree (same for both layers)
    k_deg<<<(E + 255) / 256, 256>>>(ei, E);
    k_inv<<<(NP + 255) / 256, 256>>>();

    int sgrid = (E * 8 + 255) / 256;

    // layer 1: two L2-resident half-passes
    cudaMemsetAsync(pAGGa, 0, HALF, 0);
    k_scatter_half<<<sgrid, 256>>>((const float4*)pX0, ei, E, (float*)pAGGa, 0);
    cudaMemsetAsync(pAGGb, 0, HALF, 0);
    k_scatter_half<<<sgrid, 256>>>((const float4*)pX0, ei, E, (float*)pAGGb, 8);
    k_dense_mma<<<NP / 128, 256>>>((const float*)pAGGa, (const float*)pAGGb,
                                   (const float*)pX0, W1l, b1, W1r,
                                   (float*)pX1, 1);
    // layer 2
    cudaMemsetAsync(pAGGa, 0, HALF, 0);
    k_scatter_half<<<sgrid, 256>>>((const float4*)pX1, ei, E, (float*)pAGGa, 0);
    cudaMemsetAsync(pAGGb, 0, HALF, 0);
    k_scatter_half<<<sgrid, 256>>>((const float4*)pX1, ei, E, (float*)pAGGb, 8);
    k_dense_mma<<<NP / 128, 256>>>((const float*)pAGGa, (const float*)pAGGb,
                                   (const float*)pX1, W2l, b2, W2r,
                                   (float*)pX0, 0);

    // scoring
    k_score<<<(EL * 16 + 255) / 256, 256>>>((const float*)pX0, eli,
                                            (float*)d_out, EL);
}

// round 5
// speedup vs baseline: 1.5794x; 1.5794x over previous
#include <cuda_runtime.h>
#include <cstdint>

#define NU 200000
#define NM 80000
#define NN 280000            // real nodes
#define NP 280064            // padded to 2188*128
#define H  64
#define EMAX 1250000
#define NB 274               // ceil(NP/1024)

// ---------------- scratch (device globals; no allocation allowed) ----------
__device__ float g_X0[(size_t)NP * H];    // node features layer-in / final out
__device__ float g_X1[(size_t)NP * H];    // layer-1 output
__device__ float g_MEAN[(size_t)NP * H];  // aggregated mean
__device__ int   g_CNT[NP];
__device__ int   g_OFF[NP];
__device__ int   g_CUR[NP];
__device__ float g_INV[NP];
__device__ int   g_BIN[EMAX];
__device__ int   g_BS[NB];
__device__ int   g_flag32[1];             // 1 => indices are int32, 0 => int64

// ---------------- index dtype detection ------------------------------------
__global__ void k_zero_flag() { g_flag32[0] = 0; }

__global__ void k_detect(const long long* __restrict__ ei, int ncheck) {
    int i = blockIdx.x * blockDim.x + threadIdx.x;
    if (i < ncheck) {
        long long v = ei[i];
        if (v < 0 || v >= (long long)NN) atomicOr(g_flag32, 1);
    }
}

__device__ __forceinline__ int get_idx(const void* ei, int pos, int f32) {
    if (f32) return ((const int*)ei)[pos];
    return (int)((const long long*)ei)[pos];
}

// ---------------- node init -------------------------------------------------
__global__ void k_init_movie(const float* __restrict__ movie_x,
                             const float* __restrict__ lin_W,
                             const float* __restrict__ lin_b,
                             const float* __restrict__ movie_emb,
                             float* __restrict__ X0) {
    int t = blockIdx.x * blockDim.x + threadIdx.x;
    if (t >= NM * H) return;
    int m = t >> 6, j = t & 63;
    float acc = __ldg(&lin_b[j]);
#pragma unroll
    for (int k = 0; k < 20; ++k)
        acc += __ldg(&movie_x[m * 20 + k]) * __ldg(&lin_W[j * 20 + k]);
    X0[(size_t)(NU + m) * H + j] = acc + __ldg(&movie_emb[t]);
}

// ---------------- CSR build --------------------------------------------------
__global__ void k_count(const void* __restrict__ ei, int E) {
    int e = blockIdx.x * blockDim.x + threadIdx.x;
    if (e >= E) return;
    int f = g_flag32[0];
    atomicAdd(&g_CNT[get_idx(ei, E + e, f)], 1);
}

__global__ void k_inv() {
    int i = blockIdx.x * blockDim.x + threadIdx.x;
    if (i < NP) g_INV[i] = 1.0f / fmaxf((float)g_CNT[i], 1.0f);
}

// per-block sums of CNT (1024 per block)
__global__ void k_blocksum() {
    __shared__ int sh[1024];
    int i = blockIdx.x * 1024 + threadIdx.x;
    sh[threadIdx.x] = (i < NP) ? g_CNT[i] : 0;
    __syncthreads();
    for (int s = 512; s > 0; s >>= 1) {
        if (threadIdx.x < s) sh[threadIdx.x] += sh[threadIdx.x + s];
        __syncthreads();
    }
    if (threadIdx.x == 0) g_BS[blockIdx.x] = sh[0];
}

// exclusive scan of g_BS (NB elems) in one block of 512
__global__ void k_scan_bs() {
    __shared__ int a[512], b[512];
    int t = threadIdx.x;
    int v = (t < NB) ? g_BS[t] : 0;
    a[t] = v;
    __syncthreads();
    int *in = a, *out = b;
    for (int s = 1; s < 512; s <<= 1) {
        out[t] = in[t] + ((t >= s) ? in[t - s] : 0);
        __syncthreads();
        int* tmp = in; in = out; out = tmp;
    }
    if (t < NB) g_BS[t] = in[t] - v;   // exclusive
}

// per-block exclusive scan + base -> OFF, CUR
__global__ void k_scan_local() {
    __shared__ int a[1024], b[1024];
    int t = threadIdx.x;
    int i = blockIdx.x * 1024 + t;
    int v = (i < NP) ? g_CNT[i] : 0;
    a[t] = v;
    __syncthreads();
    int *in = a, *out = b;
    for (int s = 1; s < 1024; s <<= 1) {
        out[t] = in[t] + ((t >= s) ? in[t - s] : 0);
        __syncthreads();
        int* tmp = in; in = out; out = tmp;
    }
    if (i < NP) {
        int excl = in[t] - v + g_BS[blockIdx.x];
        g_OFF[i] = excl;
        g_CUR[i] = excl;
    }
}

__global__ void k_place(const void* __restrict__ ei, int E) {
    int e = blockIdx.x * blockDim.x + threadIdx.x;
    if (e >= E) return;
    int f = g_flag32[0];
    int src = get_idx(ei, e, f);
    int dst = get_idx(ei, E + e, f);
    int pos = atomicAdd(&g_CUR[dst], 1);
    g_BIN[pos] = src;
}

// ---------------- gather-mean: MEAN[n] = (1/deg) * sum_{src in bin} X[src] --
// 16 threads per node (one float4 column each); src list broadcast per lane grp
__global__ void __launch_bounds__(256)
k_gather_mean(const float4* __restrict__ X, float4* __restrict__ MEAN) {
    int t = blockIdx.x * blockDim.x + threadIdx.x;
    int node = t >> 4, c = t & 15;
    if (node >= NP) return;
    int start = g_OFF[node];
    int cnt   = g_CNT[node];
    float inv = g_INV[node];
    float4 s = make_float4(0.f, 0.f, 0.f, 0.f);
    for (int i = 0; i < cnt; ++i) {
        int src = __ldg(&g_BIN[start + i]);
        float4 v = __ldg(&X[(size_t)src * 16 + c]);
        s.x += v.x; s.y += v.y; s.z += v.z; s.w += v.w;
    }
    s.x *= inv; s.y *= inv; s.z *= inv; s.w *= inv;
    MEAN[(size_t)node * 16 + c] = s;
}

// ---------------- tf32 helpers ----------------------------------------------
__device__ __forceinline__ uint32_t f2tf32(float x) {
    uint32_t r;
    asm("cvt.rna.tf32.f32 %0, %1;" : "=r"(r) : "f"(x));
    return r;
}

// ---------------- dense update via tensor cores ------------------------------
// out = [mean‖x](NP x 128) @ Wc(128 x 64) + b
__global__ void __launch_bounds__(256)
k_dense_mma(const float* __restrict__ MEAN, const float* __restrict__ Xin,
            const float* __restrict__ Wl, const float* __restrict__ bvec,
            const float* __restrict__ Wr, float* __restrict__ Xout,
            int do_relu) {
    __shared__ uint32_t Bs[128][72];
    __shared__ float bsh[64];

    int tid  = threadIdx.x;
    int base = blockIdx.x * 128;

    for (int i = tid; i < 128 * 64; i += 256) {
        int k = i & 127, j = i >> 7;
        float w = (k < 64) ? __ldg(&Wl[j * 64 + k]) : __ldg(&Wr[j * 64 + k - 64]);
        Bs[k][j] = f2tf32(w);
    }
    if (tid < 64) bsh[tid] = __ldg(&bvec[tid]);
    __syncthreads();

    int warp = tid >> 5, lane = tid & 31;
    int r = lane >> 2, c = lane & 3;
    int row0 = base + warp * 16 + r;        // rows row0, row0+8

    float acc[8][4];
#pragma unroll
    for (int nf = 0; nf < 8; ++nf)
#pragma unroll
        for (int i = 0; i < 4; ++i) acc[nf][i] = 0.0f;

    const float* M0  = MEAN + (size_t)row0 * 64;
    const float* M1  = MEAN + (size_t)(row0 + 8) * 64;
    const float* X0p = Xin  + (size_t)row0 * 64;
    const float* X1p = Xin  + (size_t)(row0 + 8) * 64;

#pragma unroll
    for (int ks = 0; ks < 16; ++ks) {
        int k0 = ks * 8;
        uint32_t a0, a1, a2, a3;
        if (ks < 8) {
            a0 = f2tf32(__ldg(&M0[k0 + c]));
            a1 = f2tf32(__ldg(&M1[k0 + c]));
            a2 = f2tf32(__ldg(&M0[k0 + c + 4]));
            a3 = f2tf32(__ldg(&M1[k0 + c + 4]));
        } else {
            int kk = k0 - 64;
            a0 = f2tf32(__ldg(&X0p[kk + c]));
            a1 = f2tf32(__ldg(&X1p[kk + c]));
            a2 = f2tf32(__ldg(&X0p[kk + c + 4]));
            a3 = f2tf32(__ldg(&X1p[kk + c + 4]));
        }
#pragma unroll
        for (int nf = 0; nf < 8; ++nf) {
            uint32_t b0 = Bs[k0 + c][8 * nf + r];
            uint32_t b1 = Bs[k0 + c + 4][8 * nf + r];
            asm volatile(
                "mma.sync.aligned.m16n8k8.row.col.f32.tf32.tf32.f32 "
                "{%0,%1,%2,%3}, {%4,%5,%6,%7}, {%8,%9}, {%0,%1,%2,%3};"
                : "+f"(acc[nf][0]), "+f"(acc[nf][1]),
                  "+f"(acc[nf][2]), "+f"(acc[nf][3])
                : "r"(a0), "r"(a1), "r"(a2), "r"(a3), "r"(b0), "r"(b1));
        }
    }

#pragma unroll
    for (int nf = 0; nf < 8; ++nf) {
        int col = 8 * nf + 2 * c;
        float o0 = acc[nf][0] + bsh[col];
        float o1 = acc[nf][1] + bsh[col + 1];
        float o2 = acc[nf][2] + bsh[col];
        float o3 = acc[nf][3] + bsh[col + 1];
        if (do_relu) {
            o0 = fmaxf(o0, 0.0f); o1 = fmaxf(o1, 0.0f);
            o2 = fmaxf(o2, 0.0f); o3 = fmaxf(o3, 0.0f);
        }
        *(float2*)&Xout[(size_t)row0 * 64 + col]       = make_float2(o0, o1);
        *(float2*)&Xout[(size_t)(row0 + 8) * 64 + col] = make_float2(o2, o3);
    }
}

// ---------------- scoring ---------------------------------------------------
__global__ void k_score(const float* __restrict__ X,
                        const void* __restrict__ eli,
                        float* __restrict__ out, int EL) {
    int t = blockIdx.x * blockDim.x + threadIdx.x;
    if (t >= EL * 16) return;
    int e = t >> 4, c = t & 15;
    int f = g_flag32[0];
    int u = get_idx(eli, e, f);
    int m = get_idx(eli, EL + e, f);
    const float4* X4 = (const float4*)X;
    float4 a = __ldg(&X4[(size_t)u * 16 + c]);
    float4 b = __ldg(&X4[(size_t)(NU + m) * 16 + c]);
    float p = a.x * b.x + a.y * b.y + a.z * b.z + a.w * b.w;
    p += __shfl_xor_sync(0xffffffffu, p, 8);
    p += __shfl_xor_sync(0xffffffffu, p, 4);
    p += __shfl_xor_sync(0xffffffffu, p, 2);
    p += __shfl_xor_sync(0xffffffffu, p, 1);
    if (c == 0) out[e] = p;
}

// ---------------- launch ----------------------------------------------------
extern "C" void kernel_launch(void* const* d_in, const int* in_sizes, int n_in,
                              void* d_out, int out_size) {
    const float* movie_x   = (const float*)d_in[0];
    const float* lin_W     = (const float*)d_in[3];
    const float* lin_b     = (const float*)d_in[4];
    const float* movie_emb = (const float*)d_in[2];
    const float* W1l = (const float*)d_in[5];
    const float* b1  = (const float*)d_in[6];
    const float* W1r = (const float*)d_in[7];
    const float* W2l = (const float*)d_in[8];
    const float* b2  = (const float*)d_in[9];
    const float* W2r = (const float*)d_in[10];
    const void*  ei  = d_in[11];
    const void*  eli = d_in[12];
    int E  = in_sizes[11] / 2;
    int EL = in_sizes[12] / 2;

    void *pX0, *pX1, *pMEAN, *pCNT;
    cudaGetSymbolAddress(&pX0, g_X0);
    cudaGetSymbolAddress(&pX1, g_X1);
    cudaGetSymbolAddress(&pMEAN, g_MEAN);
    cudaGetSymbolAddress(&pCNT, g_CNT);

    cudaMemsetAsync(pCNT, 0, (size_t)NP * sizeof(int), 0);
    // zero padded tail rows of X0/X1 so tail garbage stays bounded
    cudaMemsetAsync((char*)pX0 + (size_t)NN * H * sizeof(float), 0,
                    (size_t)(NP - NN) * H * sizeof(float), 0);
    cudaMemsetAsync((char*)pX1 + (size_t)NN * H * sizeof(float), 0,
                    (size_t)(NP - NN) * H * sizeof(float), 0);

    k_zero_flag<<<1, 1>>>();
    k_detect<<<4, 256>>>((const long long*)ei, 1024);

    // node features
    cudaMemcpyAsync(pX0, d_in[1], (size_t)NU * H * sizeof(float),
                    cudaMemcpyDeviceToDevice, 0);
    k_init_movie<<<(NM * H + 255) / 256, 256>>>(movie_x, lin_W, lin_b,
                                                movie_emb, (float*)pX0);

    // CSR build (shared by both layers)
    k_count<<<(E + 255) / 256, 256>>>(ei, E);
    k_inv<<<(NP + 255) / 256, 256>>>();
    k_blocksum<<<NB, 1024>>>();
    k_scan_bs<<<1, 512>>>();
    k_scan_local<<<NB, 1024>>>();
    k_place<<<(E + 255) / 256, 256>>>(ei, E);

    int ggrid = (NP * 16 + 255) / 256;

    // layer 1
    k_gather_mean<<<ggrid, 256>>>((const float4*)pX0, (float4*)pMEAN);
    k_dense_mma<<<NP / 128, 256>>>((const float*)pMEAN, (const float*)pX0,
                                   W1l, b1, W1r, (float*)pX1, 1);
    // layer 2
    k_gather_mean<<<ggrid, 256>>>((const float4*)pX1, (float4*)pMEAN);
    k_dense_mma<<<NP / 128, 256>>>((const float*)pMEAN, (const float*)pX1,
                                   W2l, b2, W2r, (float*)pX0, 0);

    // scoring
    k_score<<<(EL * 16 + 255) / 256, 256>>>((const float*)pX0, eli,
                                            (float*)d_out, EL);
}